// round 2
// baseline (speedup 1.0000x reference)
#include <cuda_runtime.h>
#include <math.h>

#define NT 2048      // tokens
#define NH 1024      // hidden
#define NE 16        // experts
#define NK 4         // top-k
#define NG 4         // groups
#define NI 512       // moe intermediate
#define NISH 1024    // shared intermediate (2*512)
#define RSCALE 2.5f
#define NA (NT*NK)   // 8192 assignments

static __device__ int   g_count[NE];
static __device__ int   g_off[NE+1];
static __device__ int   g_cur[NE];
static __device__ int   g_texp[NT*NK];
static __device__ float g_twt[NT*NK];
static __device__ int   g_tok[NA];
static __device__ float g_wslot[NA];
static __device__ int   g_slot[NT*NK];
static __device__ float g_h[(size_t)NA*NI];     // 16.8 MB
static __device__ float g_y[(size_t)NA*NH];     // 33.5 MB
static __device__ float g_shh[(size_t)NT*NISH]; // 8.4 MB

__global__ void zero_kernel() {
    if (threadIdx.x < NE) g_count[threadIdx.x] = 0;
}

// One block (128 threads) per token.
__global__ void router_kernel(const float* __restrict__ x,
                              const float* __restrict__ wr,
                              const float* __restrict__ eb) {
    const int t = blockIdx.x;
    __shared__ float xs[NH];
    __shared__ float part[128];
    __shared__ float scores[NE];
    const int tid = threadIdx.x;
    for (int i = tid; i < NH; i += 128) xs[i] = x[(size_t)t*NH + i];
    __syncthreads();
    const int e = tid >> 3, p = tid & 7;
    float s = 0.f;
    const float* w = wr + (size_t)e*NH;
    for (int i = p; i < NH; i += 8) s += xs[i] * w[i];
    part[tid] = s;
    __syncthreads();
    if (tid < NE) {
        float v = 0.f;
        #pragma unroll
        for (int j = 0; j < 8; j++) v += part[tid*8 + j];
        scores[tid] = 1.f / (1.f + expf(-v));
    }
    __syncthreads();
    if (tid == 0) {
        float sc[NE];
        #pragma unroll
        for (int i = 0; i < NE; i++) sc[i] = scores[i] + eb[i];
        // group scores = sum of top-2 within each group of 4
        float gs[NG];
        #pragma unroll
        for (int g = 0; g < NG; g++) {
            float m1 = -1e30f, m2 = -1e30f;
            #pragma unroll
            for (int j = 0; j < 4; j++) {
                float v = sc[g*4 + j];
                if (v > m1) { m2 = m1; m1 = v; } else if (v > m2) m2 = v;
            }
            gs[g] = m1 + m2;
        }
        int g1 = 0;
        for (int g = 1; g < NG; g++) if (gs[g] > gs[g1]) g1 = g;
        int g2 = -1;
        for (int g = 0; g < NG; g++) {
            if (g == g1) continue;
            if (g2 < 0 || gs[g] > gs[g2]) g2 = g;
        }
        float msk[NE];
        #pragma unroll
        for (int i = 0; i < NE; i++) {
            int gi = i >> 2;
            msk[i] = (gi == g1 || gi == g2) ? sc[i] : 0.0f;
        }
        int   idx[NK]; float tw[NK]; float sum = 0.f;
        #pragma unroll
        for (int k = 0; k < NK; k++) {
            int best = 0; float bv = -1e30f;
            for (int i = 0; i < NE; i++)
                if (msk[i] > bv) { bv = msk[i]; best = i; }
            msk[best] = -1e30f;
            idx[k] = best; tw[k] = scores[best]; sum += tw[k];
        }
        const float inv = RSCALE / (sum + 1e-20f);
        for (int k = 0; k < NK; k++) {
            g_texp[t*NK + k] = idx[k];
            g_twt[t*NK + k]  = tw[k] * inv;
            atomicAdd(&g_count[idx[k]], 1);
        }
    }
}

__global__ void prefix_kernel() {
    int o = 0;
    for (int e = 0; e < NE; e++) { g_off[e] = o; g_cur[e] = o; o += g_count[e]; }
    g_off[NE] = o;
}

__global__ void scatter_kernel() {
    int t = blockIdx.x*blockDim.x + threadIdx.x;
    if (t >= NT) return;
    for (int k = 0; k < NK; k++) {
        int e = g_texp[t*NK + k];
        int s = atomicAdd(&g_cur[e], 1);
        g_tok[s] = t;
        g_wslot[s] = g_twt[t*NK + k];
        g_slot[t*NK + k] = s;
    }
}

// ---- Tiled fp32 GEMMs: BM=BN=64, BK=16, 256 threads, 4x4 register tiles ----

// routed gate+up fused with SiLU: h[slot, i]
__global__ __launch_bounds__(256) void gateup_routed_kernel(
        const float* __restrict__ x,
        const float* __restrict__ gw,
        const float* __restrict__ uw) {
    const int e  = blockIdx.z;
    const int off = g_off[e];
    const int ne  = g_off[e+1] - off;
    const int m0  = blockIdx.x * 64;
    if (m0 >= ne) return;
    const int n0  = blockIdx.y * 64;

    __shared__ float As[16][68];
    __shared__ float Bg[16][68];
    __shared__ float Bu[16][68];
    __shared__ int toks[64];

    const int tid = threadIdx.x;
    if (tid < 64) {
        int m = m0 + tid;
        toks[tid] = (m < ne) ? g_tok[off + m] : -1;
    }
    __syncthreads();

    const int lr = tid >> 2, lc = (tid & 3) * 4;
    const int tx = tid & 15, ty = tid >> 4;
    const int tokr = toks[lr];
    const float* xr  = x + (size_t)((tokr >= 0) ? tokr : 0)*NH + lc;
    const float* gwe = gw + (size_t)e*NI*NH + (size_t)(n0 + lr)*NH + lc;
    const float* uwe = uw + (size_t)e*NI*NH + (size_t)(n0 + lr)*NH + lc;

    float ag[4][4] = {{0.f}}, au[4][4] = {{0.f}};

    for (int k0 = 0; k0 < NH; k0 += 16) {
        float4 va = (tokr >= 0) ? *(const float4*)(xr + k0) : make_float4(0,0,0,0);
        float4 vg = *(const float4*)(gwe + k0);
        float4 vu = *(const float4*)(uwe + k0);
        As[lc+0][lr]=va.x; As[lc+1][lr]=va.y; As[lc+2][lr]=va.z; As[lc+3][lr]=va.w;
        Bg[lc+0][lr]=vg.x; Bg[lc+1][lr]=vg.y; Bg[lc+2][lr]=vg.z; Bg[lc+3][lr]=vg.w;
        Bu[lc+0][lr]=vu.x; Bu[lc+1][lr]=vu.y; Bu[lc+2][lr]=vu.z; Bu[lc+3][lr]=vu.w;
        __syncthreads();
        #pragma unroll
        for (int k = 0; k < 16; k++) {
            float a[4], bg[4], bu[4];
            #pragma unroll
            for (int i = 0; i < 4; i++) a[i]  = As[k][ty*4 + i];
            #pragma unroll
            for (int j = 0; j < 4; j++) { bg[j] = Bg[k][tx*4 + j]; bu[j] = Bu[k][tx*4 + j]; }
            #pragma unroll
            for (int i = 0; i < 4; i++)
                #pragma unroll
                for (int j = 0; j < 4; j++) {
                    ag[i][j] += a[i]*bg[j];
                    au[i][j] += a[i]*bu[j];
                }
        }
        __syncthreads();
    }
    #pragma unroll
    for (int i = 0; i < 4; i++) {
        int m = m0 + ty*4 + i;
        if (m >= ne) continue;
        size_t r = (size_t)(off + m);
        #pragma unroll
        for (int j = 0; j < 4; j++) {
            float gv = ag[i][j], uv = au[i][j];
            float hv = gv / (1.f + expf(-gv)) * uv;
            g_h[r*NI + n0 + tx*4 + j] = hv;
        }
    }
}

// routed down proj * routing weight: y[slot, h]
__global__ __launch_bounds__(256) void down_routed_kernel(const float* __restrict__ dw) {
    const int e  = blockIdx.z;
    const int off = g_off[e];
    const int ne  = g_off[e+1] - off;
    const int m0  = blockIdx.x * 64;
    if (m0 >= ne) return;
    const int n0  = blockIdx.y * 64;

    __shared__ float As[16][68];
    __shared__ float Bs[16][68];
    const int tid = threadIdx.x;
    const int lr = tid >> 2, lc = (tid & 3) * 4;
    const int tx = tid & 15, ty = tid >> 4;
    const bool vr = (m0 + lr) < ne;
    const float* ar = g_h + (size_t)(off + (vr ? (m0 + lr) : 0))*NI + lc;
    const float* br = dw + (size_t)e*NH*NI + (size_t)(n0 + lr)*NI + lc;

    float acc[4][4] = {{0.f}};
    for (int k0 = 0; k0 < NI; k0 += 16) {
        float4 va = vr ? *(const float4*)(ar + k0) : make_float4(0,0,0,0);
        float4 vb = *(const float4*)(br + k0);
        As[lc+0][lr]=va.x; As[lc+1][lr]=va.y; As[lc+2][lr]=va.z; As[lc+3][lr]=va.w;
        Bs[lc+0][lr]=vb.x; Bs[lc+1][lr]=vb.y; Bs[lc+2][lr]=vb.z; Bs[lc+3][lr]=vb.w;
        __syncthreads();
        #pragma unroll
        for (int k = 0; k < 16; k++) {
            float a[4], b[4];
            #pragma unroll
            for (int i = 0; i < 4; i++) a[i] = As[k][ty*4 + i];
            #pragma unroll
            for (int j = 0; j < 4; j++) b[j] = Bs[k][tx*4 + j];
            #pragma unroll
            for (int i = 0; i < 4; i++)
                #pragma unroll
                for (int j = 0; j < 4; j++) acc[i][j] += a[i]*b[j];
        }
        __syncthreads();
    }
    #pragma unroll
    for (int i = 0; i < 4; i++) {
        int m = m0 + ty*4 + i;
        if (m >= ne) continue;
        size_t r = (size_t)(off + m);
        float w = g_wslot[r];
        #pragma unroll
        for (int j = 0; j < 4; j++)
            g_y[r*NH + n0 + tx*4 + j] = acc[i][j] * w;
    }
}

// shared gate+up fused with SiLU: g_shh[t, i]
__global__ __launch_bounds__(256) void gateup_shared_kernel(
        const float* __restrict__ x,
        const float* __restrict__ gw,
        const float* __restrict__ uw) {
    const int m0 = blockIdx.x * 64;
    const int n0 = blockIdx.y * 64;
    __shared__ float As[16][68];
    __shared__ float Bg[16][68];
    __shared__ float Bu[16][68];
    const int tid = threadIdx.x;
    const int lr = tid >> 2, lc = (tid & 3) * 4;
    const int tx = tid & 15, ty = tid >> 4;
    const float* xr  = x  + (size_t)(m0 + lr)*NH + lc;
    const float* gwe = gw + (size_t)(n0 + lr)*NH + lc;
    const float* uwe = uw + (size_t)(n0 + lr)*NH + lc;

    float ag[4][4] = {{0.f}}, au[4][4] = {{0.f}};
    for (int k0 = 0; k0 < NH; k0 += 16) {
        float4 va = *(const float4*)(xr  + k0);
        float4 vg = *(const float4*)(gwe + k0);
        float4 vu = *(const float4*)(uwe + k0);
        As[lc+0][lr]=va.x; As[lc+1][lr]=va.y; As[lc+2][lr]=va.z; As[lc+3][lr]=va.w;
        Bg[lc+0][lr]=vg.x; Bg[lc+1][lr]=vg.y; Bg[lc+2][lr]=vg.z; Bg[lc+3][lr]=vg.w;
        Bu[lc+0][lr]=vu.x; Bu[lc+1][lr]=vu.y; Bu[lc+2][lr]=vu.z; Bu[lc+3][lr]=vu.w;
        __syncthreads();
        #pragma unroll
        for (int k = 0; k < 16; k++) {
            float a[4], bg[4], bu[4];
            #pragma unroll
            for (int i = 0; i < 4; i++) a[i]  = As[k][ty*4 + i];
            #pragma unroll
            for (int j = 0; j < 4; j++) { bg[j] = Bg[k][tx*4 + j]; bu[j] = Bu[k][tx*4 + j]; }
            #pragma unroll
            for (int i = 0; i < 4; i++)
                #pragma unroll
                for (int j = 0; j < 4; j++) {
                    ag[i][j] += a[i]*bg[j];
                    au[i][j] += a[i]*bu[j];
                }
        }
        __syncthreads();
    }
    #pragma unroll
    for (int i = 0; i < 4; i++) {
        size_t m = (size_t)(m0 + ty*4 + i);
        #pragma unroll
        for (int j = 0; j < 4; j++) {
            float gv = ag[i][j], uv = au[i][j];
            g_shh[m*NISH + n0 + tx*4 + j] = gv / (1.f + expf(-gv)) * uv;
        }
    }
}

// shared down proj, writes out (covers every element of d_out)
__global__ __launch_bounds__(256) void down_shared_kernel(
        const float* __restrict__ dw, float* __restrict__ out) {
    const int m0 = blockIdx.x * 64;
    const int n0 = blockIdx.y * 64;
    __shared__ float As[16][68];
    __shared__ float Bs[16][68];
    const int tid = threadIdx.x;
    const int lr = tid >> 2, lc = (tid & 3) * 4;
    const int tx = tid & 15, ty = tid >> 4;
    const float* ar = g_shh + (size_t)(m0 + lr)*NISH + lc;
    const float* br = dw + (size_t)(n0 + lr)*NISH + lc;

    float acc[4][4] = {{0.f}};
    for (int k0 = 0; k0 < NISH; k0 += 16) {
        float4 va = *(const float4*)(ar + k0);
        float4 vb = *(const float4*)(br + k0);
        As[lc+0][lr]=va.x; As[lc+1][lr]=va.y; As[lc+2][lr]=va.z; As[lc+3][lr]=va.w;
        Bs[lc+0][lr]=vb.x; Bs[lc+1][lr]=vb.y; Bs[lc+2][lr]=vb.z; Bs[lc+3][lr]=vb.w;
        __syncthreads();
        #pragma unroll
        for (int k = 0; k < 16; k++) {
            float a[4], b[4];
            #pragma unroll
            for (int i = 0; i < 4; i++) a[i] = As[k][ty*4 + i];
            #pragma unroll
            for (int j = 0; j < 4; j++) b[j] = Bs[k][tx*4 + j];
            #pragma unroll
            for (int i = 0; i < 4; i++)
                #pragma unroll
                for (int j = 0; j < 4; j++) acc[i][j] += a[i]*b[j];
        }
        __syncthreads();
    }
    #pragma unroll
    for (int i = 0; i < 4; i++) {
        size_t m = (size_t)(m0 + ty*4 + i);
        #pragma unroll
        for (int j = 0; j < 4; j++)
            out[m*NH + n0 + tx*4 + j] = acc[i][j];
    }
}

// out[t] += sum_k y[slot[t,k]]  (fixed k order -> deterministic)
__global__ void combine_kernel(float* __restrict__ out) {
    const int t = blockIdx.x;
    const int c = threadIdx.x; // 256 float4s per row
    const int s0 = g_slot[t*4+0], s1 = g_slot[t*4+1],
              s2 = g_slot[t*4+2], s3 = g_slot[t*4+3];
    const float4* y4 = (const float4*)g_y;
    float4* o4 = (float4*)out;
    float4 o = o4[(size_t)t*256 + c];
    float4 a = y4[(size_t)s0*256 + c];
    float4 b = y4[(size_t)s1*256 + c];
    float4 cc = y4[(size_t)s2*256 + c];
    float4 d = y4[(size_t)s3*256 + c];
    o.x += a.x + b.x + cc.x + d.x;
    o.y += a.y + b.y + cc.y + d.y;
    o.z += a.z + b.z + cc.z + d.z;
    o.w += a.w + b.w + cc.w + d.w;
    o4[(size_t)t*256 + c] = o;
}

extern "C" void kernel_launch(void* const* d_in, const int* in_sizes, int n_in,
                              void* d_out, int out_size) {
    const float* x   = (const float*)d_in[0];
    const float* wr  = (const float*)d_in[1];
    const float* eb  = (const float*)d_in[2];
    const float* gw  = (const float*)d_in[3];
    const float* uw  = (const float*)d_in[4];
    const float* dw  = (const float*)d_in[5];
    const float* sgw = (const float*)d_in[6];
    const float* suw = (const float*)d_in[7];
    const float* sdw = (const float*)d_in[8];
    float* out = (float*)d_out;
    (void)in_sizes; (void)n_in; (void)out_size;

    zero_kernel<<<1, 32>>>();
    router_kernel<<<NT, 128>>>(x, wr, eb);
    prefix_kernel<<<1, 1>>>();
    scatter_kernel<<<8, 256>>>();
    gateup_routed_kernel<<<dim3(32, 8, 16), 256>>>(x, gw, uw);
    down_routed_kernel<<<dim3(32, 16, 16), 256>>>(dw);
    gateup_shared_kernel<<<dim3(32, 16), 256>>>(x, sgw, suw);
    down_shared_kernel<<<dim3(32, 16), 256>>>(sdw, out);
    combine_kernel<<<NT, 256>>>(out);
}

// round 4
// speedup vs baseline: 2.3659x; 2.3659x over previous
#include <cuda_runtime.h>
#include <cuda_bf16.h>
#include <cstdint>
#include <math.h>

#define NT 2048      // tokens
#define NH 1024      // hidden
#define NE 16        // experts
#define NK 4         // top-k
#define NG 4         // groups
#define NI 512       // moe intermediate
#define NISH 1024    // shared intermediate
#define RSCALE 2.5f
#define NA (NT*NK)
#define SK 40        // smem row stride in halves (32 + 8 pad, rows 16B aligned)

// ---------------- scratch ----------------
static __device__ int   g_count[NE];
static __device__ int   g_off[NE+1];
static __device__ int   g_cur[NE];
static __device__ int   g_texp[NT*NK];
static __device__ float g_twt[NT*NK];
static __device__ int   g_tok[NA];
static __device__ float g_wslot[NA];
static __device__ int   g_slot[NT*NK];
static __device__ __nv_bfloat16 g_h_hi[(size_t)NA*NI];
static __device__ __nv_bfloat16 g_h_lo[(size_t)NA*NI];
static __device__ __nv_bfloat16 g_sh_hi[(size_t)NT*NISH];
static __device__ __nv_bfloat16 g_sh_lo[(size_t)NT*NISH];
static __device__ float g_y[(size_t)NA*NH];

// ---------------- helpers ----------------
__device__ __forceinline__ uint32_t smem_u32(const void* p) {
    uint32_t a;
    asm("{ .reg .u64 t; cvta.to.shared.u64 t, %1; cvt.u32.u64 %0, t; }" : "=r"(a) : "l"(p));
    return a;
}

__device__ __forceinline__ void ldsm4(uint32_t& a0, uint32_t& a1, uint32_t& a2, uint32_t& a3,
                                      uint32_t addr) {
    asm volatile("ldmatrix.sync.aligned.m8n8.x4.shared.b16 {%0,%1,%2,%3}, [%4];"
        : "=r"(a0), "=r"(a1), "=r"(a2), "=r"(a3) : "r"(addr));
}
__device__ __forceinline__ void ldsm2(uint32_t& b0, uint32_t& b1, uint32_t addr) {
    asm volatile("ldmatrix.sync.aligned.m8n8.x2.shared.b16 {%0,%1}, [%2];"
        : "=r"(b0), "=r"(b1) : "r"(addr));
}
__device__ __forceinline__ void mma16816(float* c, const uint32_t* a, const uint32_t* b) {
    asm volatile("mma.sync.aligned.m16n8k16.row.col.f32.bf16.bf16.f32 "
        "{%0,%1,%2,%3}, {%4,%5,%6,%7}, {%8,%9}, {%0,%1,%2,%3};"
        : "+f"(c[0]), "+f"(c[1]), "+f"(c[2]), "+f"(c[3])
        : "r"(a[0]), "r"(a[1]), "r"(a[2]), "r"(a[3]), "r"(b[0]), "r"(b[1]));
}

__device__ __forceinline__ void st_pair(__nv_bfloat16* bh, __nv_bfloat16* bl,
                                        int idx, float2 v) {
    __nv_bfloat162 h, l;
    h.x = __float2bfloat16(v.x); h.y = __float2bfloat16(v.y);
    l.x = __float2bfloat16(v.x - __bfloat162float(h.x));
    l.y = __float2bfloat16(v.y - __bfloat162float(h.y));
    *(__nv_bfloat162*)(bh + idx) = h;
    *(__nv_bfloat162*)(bl + idx) = l;
}

// ---------------- routing ----------------
__global__ void zero_kernel() {
    if (threadIdx.x < NE) g_count[threadIdx.x] = 0;
}

__global__ void router_kernel(const float* __restrict__ x,
                              const float* __restrict__ wr,
                              const float* __restrict__ eb) {
    const int t = blockIdx.x;
    __shared__ float xs[NH];
    __shared__ float part[128];
    __shared__ float scores[NE];
    const int tid = threadIdx.x;
    for (int i = tid; i < NH; i += 128) xs[i] = x[(size_t)t*NH + i];
    __syncthreads();
    const int e = tid >> 3, p = tid & 7;
    float s = 0.f;
    const float* w = wr + (size_t)e*NH;
    for (int i = p; i < NH; i += 8) s += xs[i] * w[i];
    part[tid] = s;
    __syncthreads();
    if (tid < NE) {
        float v = 0.f;
        #pragma unroll
        for (int j = 0; j < 8; j++) v += part[tid*8 + j];
        scores[tid] = 1.f / (1.f + expf(-v));
    }
    __syncthreads();
    if (tid == 0) {
        float sc[NE];
        #pragma unroll
        for (int i = 0; i < NE; i++) sc[i] = scores[i] + eb[i];
        float gs[NG];
        #pragma unroll
        for (int g = 0; g < NG; g++) {
            float m1 = -1e30f, m2 = -1e30f;
            #pragma unroll
            for (int j = 0; j < 4; j++) {
                float v = sc[g*4 + j];
                if (v > m1) { m2 = m1; m1 = v; } else if (v > m2) m2 = v;
            }
            gs[g] = m1 + m2;
        }
        int g1 = 0;
        for (int g = 1; g < NG; g++) if (gs[g] > gs[g1]) g1 = g;
        int g2 = -1;
        for (int g = 0; g < NG; g++) {
            if (g == g1) continue;
            if (g2 < 0 || gs[g] > gs[g2]) g2 = g;
        }
        float msk[NE];
        #pragma unroll
        for (int i = 0; i < NE; i++) {
            int gi = i >> 2;
            msk[i] = (gi == g1 || gi == g2) ? sc[i] : 0.0f;
        }
        int idx[NK]; float tw[NK]; float sum = 0.f;
        #pragma unroll
        for (int k = 0; k < NK; k++) {
            int best = 0; float bv = -1e30f;
            for (int i = 0; i < NE; i++)
                if (msk[i] > bv) { bv = msk[i]; best = i; }
            msk[best] = -1e30f;
            idx[k] = best; tw[k] = scores[best]; sum += tw[k];
        }
        const float inv = RSCALE / (sum + 1e-20f);
        for (int k = 0; k < NK; k++) {
            g_texp[t*NK + k] = idx[k];
            g_twt[t*NK + k]  = tw[k] * inv;
            atomicAdd(&g_count[idx[k]], 1);
        }
    }
}

__global__ void prefix_kernel() {
    int o = 0;
    for (int e = 0; e < NE; e++) { g_off[e] = o; g_cur[e] = o; o += g_count[e]; }
    g_off[NE] = o;
}

__global__ void scatter_kernel() {
    int t = blockIdx.x*blockDim.x + threadIdx.x;
    if (t >= NT) return;
    for (int k = 0; k < NK; k++) {
        int e = g_texp[t*NK + k];
        int s = atomicAdd(&g_cur[e], 1);
        g_tok[s] = t;
        g_wslot[s] = g_twt[t*NK + k];
        g_slot[t*NK + k] = s;
    }
}

// ---------------- gate+up fused MMA kernel ----------------
// CTA: 128 (m) x 64 (n) per gemm (gate and up both). 8 warps: wr = wid>>1 in
// [0,4) covering 32 m each; wc = wid&1 covering 32 n each. Warp tile 32x32:
// 2 m-frags x 4 n-frags per gemm. Split-bf16: acc += Ah*Bh + Ah*Bl + Al*Bh.
__global__ __launch_bounds__(256) void gateup_mma(
    const float* __restrict__ x, const float* __restrict__ gwb,
    const float* __restrict__ uwb, size_t estride, int routed)
{
    const int e = blockIdx.z;
    const int off = routed ? g_off[e] : 0;
    const int ne  = routed ? (g_off[e+1] - off) : NT;
    const int m0 = blockIdx.x * 128;
    if (m0 >= ne) return;
    const int n0 = blockIdx.y * 64;
    const int outw = routed ? NI : NISH;
    __nv_bfloat16* hhi = routed ? g_h_hi : g_sh_hi;
    __nv_bfloat16* hlo = routed ? g_h_lo : g_sh_lo;

    __shared__ __nv_bfloat16 sAh[128*SK], sAl[128*SK];
    __shared__ __nv_bfloat16 sGh[64*SK],  sGl[64*SK];
    __shared__ __nv_bfloat16 sUh[64*SK],  sUl[64*SK];
    __shared__ int toks[128];

    const int tid = threadIdx.x, wid = tid >> 5, lid = tid & 31;
    const int wr = wid >> 1, wc = wid & 1;
    if (tid < 128) {
        int m = m0 + tid;
        toks[tid] = (m < ne) ? (routed ? g_tok[off + m] : m) : -1;
    }
    __syncthreads();

    const float* gw = gwb + (size_t)e * estride;
    const float* uw = uwb + (size_t)e * estride;

    float accg[2][4][4] = {}, accu[2][4][4] = {};

    const int lrow = tid >> 4;          // 0..15
    const int kp   = (tid & 15) * 2;    // 0..30 even

    for (int c = 0; c < NH/32; ++c) {
        const int k0 = c * 32;
        float2 ra[8], rg[4], ru[4];
        #pragma unroll
        for (int i = 0; i < 8; i++) {
            int row = lrow + 16*i;
            int tok = toks[row];
            ra[i] = (tok >= 0) ? *(const float2*)(x + (size_t)tok*NH + k0 + kp)
                               : make_float2(0.f, 0.f);
        }
        #pragma unroll
        for (int i = 0; i < 4; i++) {
            int row = lrow + 16*i;      // 0..63
            rg[i] = *(const float2*)(gw + (size_t)(n0+row)*NH + k0 + kp);
            ru[i] = *(const float2*)(uw + (size_t)(n0+row)*NH + k0 + kp);
        }
        __syncthreads();   // previous chunk's compute done
        #pragma unroll
        for (int i = 0; i < 8; i++) st_pair(sAh, sAl, (lrow + 16*i)*SK + kp, ra[i]);
        #pragma unroll
        for (int i = 0; i < 4; i++) {
            st_pair(sGh, sGl, (lrow + 16*i)*SK + kp, rg[i]);
            st_pair(sUh, sUl, (lrow + 16*i)*SK + kp, ru[i]);
        }
        __syncthreads();
        #pragma unroll
        for (int ks = 0; ks < 32; ks += 16) {
            uint32_t ah[2][4], al[2][4];
            #pragma unroll
            for (int mi = 0; mi < 2; mi++) {
                uint32_t o = ((wr*32 + mi*16 + (lid & 15))*SK + ks + (lid >> 4)*8) * 2;
                ldsm4(ah[mi][0], ah[mi][1], ah[mi][2], ah[mi][3], smem_u32(sAh) + o);
                ldsm4(al[mi][0], al[mi][1], al[mi][2], al[mi][3], smem_u32(sAl) + o);
            }
            #pragma unroll
            for (int ni = 0; ni < 4; ni++) {
                uint32_t o = ((wc*32 + ni*8 + (lid & 7))*SK + ks + ((lid >> 3) & 1)*8) * 2;
                uint32_t bgh[2], bgl[2], buh[2], bul[2];
                ldsm2(bgh[0], bgh[1], smem_u32(sGh) + o);
                ldsm2(bgl[0], bgl[1], smem_u32(sGl) + o);
                ldsm2(buh[0], buh[1], smem_u32(sUh) + o);
                ldsm2(bul[0], bul[1], smem_u32(sUl) + o);
                #pragma unroll
                for (int mi = 0; mi < 2; mi++) {
                    mma16816(accg[mi][ni], ah[mi], bgh);
                    mma16816(accg[mi][ni], ah[mi], bgl);
                    mma16816(accg[mi][ni], al[mi], bgh);
                    mma16816(accu[mi][ni], ah[mi], buh);
                    mma16816(accu[mi][ni], ah[mi], bul);
                    mma16816(accu[mi][ni], al[mi], buh);
                }
            }
        }
    }
    // epilogue: silu(g)*u, write hi/lo bf16
    #pragma unroll
    for (int mi = 0; mi < 2; mi++) {
        int r0 = wr*32 + mi*16 + (lid >> 2);
        #pragma unroll
        for (int half = 0; half < 2; half++) {
            int m = m0 + r0 + half*8;
            if (m >= ne) continue;
            size_t orow = (size_t)(off + m) * outw;
            #pragma unroll
            for (int ni = 0; ni < 4; ni++) {
                float g0 = accg[mi][ni][half*2+0], g1 = accg[mi][ni][half*2+1];
                float u0 = accu[mi][ni][half*2+0], u1 = accu[mi][ni][half*2+1];
                float h0 = g0 / (1.f + expf(-g0)) * u0;
                float h1 = g1 / (1.f + expf(-g1)) * u1;
                int nc = n0 + wc*32 + ni*8 + (lid & 3)*2;
                __nv_bfloat162 hh, hl;
                hh.x = __float2bfloat16(h0); hh.y = __float2bfloat16(h1);
                hl.x = __float2bfloat16(h0 - __bfloat162float(hh.x));
                hl.y = __float2bfloat16(h1 - __bfloat162float(hh.y));
                *(__nv_bfloat162*)(hhi + orow + nc) = hh;
                *(__nv_bfloat162*)(hlo + orow + nc) = hl;
            }
        }
    }
}

// ---------------- down projection MMA kernel ----------------
// CTA: 128 (m) x 128 (n). 8 warps: wr = wid>>2 in [0,2) covering 64 m;
// wc = wid&3 covering 32 n. Warp tile 64x32: 4 m-frags x 4 n-frags.
__global__ __launch_bounds__(256) void down_mma(
    const float* __restrict__ dwb, float* __restrict__ outp,
    int Kd, size_t estride, int routed)
{
    const int e = blockIdx.z;
    const int off = routed ? g_off[e] : 0;
    const int ne  = routed ? (g_off[e+1] - off) : NT;
    const int m0 = blockIdx.x * 128;
    if (m0 >= ne) return;
    const int n0 = blockIdx.y * 128;
    const __nv_bfloat16* ahi = routed ? g_h_hi : g_sh_hi;
    const __nv_bfloat16* alo = routed ? g_h_lo : g_sh_lo;
    float* dst = routed ? g_y : outp;

    __shared__ __nv_bfloat16 sAh[128*SK], sAl[128*SK];
    __shared__ __nv_bfloat16 sBh[128*SK], sBl[128*SK];

    const int tid = threadIdx.x, wid = tid >> 5, lid = tid & 31;
    const int wr = wid >> 2, wc = wid & 3;
    const float* dw = dwb + (size_t)e * estride;

    float acc[4][4][4] = {};
    const int lrow = tid >> 4;
    const int kp   = (tid & 15) * 2;

    for (int c = 0; c < Kd/32; ++c) {
        const int k0 = c * 32;
        uint32_t rah[8], ral[8];
        float2 rb[8];
        #pragma unroll
        for (int i = 0; i < 8; i++) {
            int row = lrow + 16*i;
            int m = m0 + row;
            if (m < ne) {
                size_t so = (size_t)(off + m) * Kd + k0 + kp;
                rah[i] = *(const uint32_t*)(ahi + so);
                ral[i] = *(const uint32_t*)(alo + so);
            } else { rah[i] = 0u; ral[i] = 0u; }
            rb[i] = *(const float2*)(dw + (size_t)(n0+row)*Kd + k0 + kp);
        }
        __syncthreads();
        #pragma unroll
        for (int i = 0; i < 8; i++) {
            int idx = (lrow + 16*i)*SK + kp;
            *(uint32_t*)(sAh + idx) = rah[i];
            *(uint32_t*)(sAl + idx) = ral[i];
            st_pair(sBh, sBl, idx, rb[i]);
        }
        __syncthreads();
        #pragma unroll
        for (int ks = 0; ks < 32; ks += 16) {
            uint32_t ah[4][4], al[4][4];
            #pragma unroll
            for (int mi = 0; mi < 4; mi++) {
                uint32_t o = ((wr*64 + mi*16 + (lid & 15))*SK + ks + (lid >> 4)*8) * 2;
                ldsm4(ah[mi][0], ah[mi][1], ah[mi][2], ah[mi][3], smem_u32(sAh) + o);
                ldsm4(al[mi][0], al[mi][1], al[mi][2], al[mi][3], smem_u32(sAl) + o);
            }
            #pragma unroll
            for (int ni = 0; ni < 4; ni++) {
                uint32_t o = ((wc*32 + ni*8 + (lid & 7))*SK + ks + ((lid >> 3) & 1)*8) * 2;
                uint32_t bh[2], bl[2];
                ldsm2(bh[0], bh[1], smem_u32(sBh) + o);
                ldsm2(bl[0], bl[1], smem_u32(sBl) + o);
                #pragma unroll
                for (int mi = 0; mi < 4; mi++) {
                    mma16816(acc[mi][ni], ah[mi], bh);
                    mma16816(acc[mi][ni], ah[mi], bl);
                    mma16816(acc[mi][ni], al[mi], bh);
                }
            }
        }
    }
    // epilogue
    #pragma unroll
    for (int mi = 0; mi < 4; mi++) {
        int r0 = wr*64 + mi*16 + (lid >> 2);
        #pragma unroll
        for (int half = 0; half < 2; half++) {
            int m = m0 + r0 + half*8;
            if (m >= ne) continue;
            float w = routed ? g_wslot[off + m] : 1.f;
            size_t orow = (size_t)(off + m) * NH;
            #pragma unroll
            for (int ni = 0; ni < 4; ni++) {
                int nc = n0 + wc*32 + ni*8 + (lid & 3)*2;
                float2 o;
                o.x = acc[mi][ni][half*2+0] * w;
                o.y = acc[mi][ni][half*2+1] * w;
                *(float2*)(dst + orow + nc) = o;
            }
        }
    }
}

// out[t] += sum_k y[slot[t,k]]  (fixed order -> deterministic)
__global__ void combine_kernel(float* __restrict__ out) {
    const int t = blockIdx.x;
    const int c = threadIdx.x;
    const int s0 = g_slot[t*4+0], s1 = g_slot[t*4+1],
              s2 = g_slot[t*4+2], s3 = g_slot[t*4+3];
    const float4* y4 = (const float4*)g_y;
    float4* o4 = (float4*)out;
    float4 o = o4[(size_t)t*256 + c];
    float4 a = y4[(size_t)s0*256 + c];
    float4 b = y4[(size_t)s1*256 + c];
    float4 cc = y4[(size_t)s2*256 + c];
    float4 d = y4[(size_t)s3*256 + c];
    o.x += a.x + b.x + cc.x + d.x;
    o.y += a.y + b.y + cc.y + d.y;
    o.z += a.z + b.z + cc.z + d.z;
    o.w += a.w + b.w + cc.w + d.w;
    o4[(size_t)t*256 + c] = o;
}

extern "C" void kernel_launch(void* const* d_in, const int* in_sizes, int n_in,
                              void* d_out, int out_size) {
    const float* x   = (const float*)d_in[0];
    const float* wr  = (const float*)d_in[1];
    const float* eb  = (const float*)d_in[2];
    const float* gw  = (const float*)d_in[3];
    const float* uw  = (const float*)d_in[4];
    const float* dw  = (const float*)d_in[5];
    const float* sgw = (const float*)d_in[6];
    const float* suw = (const float*)d_in[7];
    const float* sdw = (const float*)d_in[8];
    float* out = (float*)d_out;
    (void)in_sizes; (void)n_in; (void)out_size;

    zero_kernel<<<1, 32>>>();
    router_kernel<<<NT, 128>>>(x, wr, eb);
    prefix_kernel<<<1, 1>>>();
    scatter_kernel<<<8, 256>>>();

    // routed gate+up: rows = expert buckets, N = 512, K = 1024
    gateup_mma<<<dim3(64, NI/64, NE), 256>>>(x, gw, uw, (size_t)NI*NH, 1);
    // shared gate+up: rows = all tokens, N = 1024, K = 1024
    gateup_mma<<<dim3(NT/128, NISH/64, 1), 256>>>(x, sgw, suw, 0, 0);
    // routed down: y = h @ dw^T * w  (K = 512, N = 1024)
    down_mma<<<dim3(64, NH/128, NE), 256>>>(dw, out, NI, (size_t)NH*NI, 1);
    // shared down: writes out directly (K = 1024, N = 1024)
    down_mma<<<dim3(NT/128, NH/128, 1), 256>>>(sdw, out, NISH, 0, 0);

    combine_kernel<<<NT, 256>>>(out);
}

// round 5
// speedup vs baseline: 2.6260x; 1.1099x over previous
#include <cuda_runtime.h>
#include <cuda_fp16.h>
#include <cstdint>
#include <math.h>

#define NT 2048      // tokens
#define NH 1024      // hidden
#define NE 16        // experts
#define NK 4         // top-k
#define NG 4         // groups
#define NI 512       // moe intermediate
#define NISH 1024    // shared intermediate
#define RSCALE 2.5f
#define NA (NT*NK)
#define SK 40        // smem row stride in halves (32 + 8 pad)

// ---------------- scratch ----------------
static __device__ int   g_count[NE];
static __device__ int   g_off[NE+1];
static __device__ int   g_cur[NE];
static __device__ int   g_texp[NT*NK];
static __device__ float g_twt[NT*NK];
static __device__ int   g_tok[NA];
static __device__ float g_wslot[NA];
static __device__ int   g_slot[NT*NK];
static __device__ float g_y[(size_t)NA*NH];

// fp16 planes (pre-converted once per launch)
static __device__ half g_xh [(size_t)NT*NH];
static __device__ half g_hh [(size_t)NA*NI];        // routed h
static __device__ half g_shh[(size_t)NT*NISH];      // shared h
static __device__ half g_gwh [(size_t)NE*NI*NH],  g_gwls[(size_t)NE*NI*NH];
static __device__ half g_uwh [(size_t)NE*NI*NH],  g_uwls[(size_t)NE*NI*NH];
static __device__ half g_dwh [(size_t)NE*NH*NI],  g_dwls[(size_t)NE*NH*NI];
static __device__ half g_sgwh[(size_t)NISH*NH],   g_sgwls[(size_t)NISH*NH];
static __device__ half g_suwh[(size_t)NISH*NH],   g_suwls[(size_t)NISH*NH];
static __device__ half g_sdwh[(size_t)NH*NISH],   g_sdwls[(size_t)NH*NISH];

// ---------------- asm helpers ----------------
__device__ __forceinline__ uint32_t smem_u32(const void* p) {
    uint32_t a;
    asm("{ .reg .u64 t; cvta.to.shared.u64 t, %1; cvt.u32.u64 %0, t; }" : "=r"(a) : "l"(p));
    return a;
}
__device__ __forceinline__ void cpa16(uint32_t dst, const void* src, int sz) {
    asm volatile("cp.async.cg.shared.global [%0], [%1], 16, %2;"
        :: "r"(dst), "l"(src), "r"(sz) : "memory");
}
#define CP_COMMIT() asm volatile("cp.async.commit_group;" ::: "memory")
#define CP_WAIT1()  asm volatile("cp.async.wait_group 1;" ::: "memory")
#define CP_WAIT0()  asm volatile("cp.async.wait_group 0;" ::: "memory")

__device__ __forceinline__ void ldsm4(uint32_t& a0, uint32_t& a1, uint32_t& a2, uint32_t& a3,
                                      uint32_t addr) {
    asm volatile("ldmatrix.sync.aligned.m8n8.x4.shared.b16 {%0,%1,%2,%3}, [%4];"
        : "=r"(a0), "=r"(a1), "=r"(a2), "=r"(a3) : "r"(addr));
}
__device__ __forceinline__ void mma16816(float* c, const uint32_t* a, const uint32_t* b) {
    asm volatile("mma.sync.aligned.m16n8k16.row.col.f32.f16.f16.f32 "
        "{%0,%1,%2,%3}, {%4,%5,%6,%7}, {%8,%9}, {%0,%1,%2,%3};"
        : "+f"(c[0]), "+f"(c[1]), "+f"(c[2]), "+f"(c[3])
        : "r"(a[0]), "r"(a[1]), "r"(a[2]), "r"(a[3]), "r"(b[0]), "r"(b[1]));
}
__device__ __forceinline__ uint32_t hscale(uint32_t a) {   // * 2^-10 per half
    uint32_t r;
    asm("mul.f16x2 %0, %1, %2;" : "=r"(r) : "r"(a), "r"(0x14001400u));
    return r;
}

// ---------------- conversion kernels ----------------
__global__ void conv_pair_kernel(const float* __restrict__ src,
                                 half* __restrict__ hi, half* __restrict__ ls, int n) {
    int i = (blockIdx.x*256 + threadIdx.x)*4;
    if (i >= n) return;
    float4 v = *(const float4*)(src + i);
    half h0 = __float2half(v.x), h1 = __float2half(v.y),
         h2 = __float2half(v.z), h3 = __float2half(v.w);
    half l0 = __float2half((v.x - __half2float(h0))*1024.f);
    half l1 = __float2half((v.y - __half2float(h1))*1024.f);
    half l2 = __float2half((v.z - __half2float(h2))*1024.f);
    half l3 = __float2half((v.w - __half2float(h3))*1024.f);
    *(__half2*)(hi + i)     = __half2(h0, h1);
    *(__half2*)(hi + i + 2) = __half2(h2, h3);
    *(__half2*)(ls + i)     = __half2(l0, l1);
    *(__half2*)(ls + i + 2) = __half2(l2, l3);
}
__global__ void conv_hi_kernel(const float* __restrict__ src, half* __restrict__ hi, int n) {
    int i = (blockIdx.x*256 + threadIdx.x)*4;
    if (i >= n) return;
    float4 v = *(const float4*)(src + i);
    *(__half2*)(hi + i)     = __half2(__float2half(v.x), __float2half(v.y));
    *(__half2*)(hi + i + 2) = __half2(__float2half(v.z), __float2half(v.w));
}

// ---------------- routing ----------------
__global__ void zero_kernel() {
    if (threadIdx.x < NE) g_count[threadIdx.x] = 0;
}

__global__ void router_kernel(const float* __restrict__ x,
                              const float* __restrict__ wr,
                              const float* __restrict__ eb) {
    const int t = blockIdx.x;
    __shared__ float xs[NH];
    __shared__ float part[128];
    __shared__ float scores[NE];
    const int tid = threadIdx.x;
    for (int i = tid; i < NH; i += 128) xs[i] = x[(size_t)t*NH + i];
    __syncthreads();
    const int e = tid >> 3, p = tid & 7;
    float s = 0.f;
    const float* w = wr + (size_t)e*NH;
    for (int i = p; i < NH; i += 8) s += xs[i] * w[i];
    part[tid] = s;
    __syncthreads();
    if (tid < NE) {
        float v = 0.f;
        #pragma unroll
        for (int j = 0; j < 8; j++) v += part[tid*8 + j];
        scores[tid] = 1.f / (1.f + expf(-v));
    }
    __syncthreads();
    if (tid == 0) {
        float sc[NE];
        #pragma unroll
        for (int i = 0; i < NE; i++) sc[i] = scores[i] + eb[i];
        float gs[NG];
        #pragma unroll
        for (int g = 0; g < NG; g++) {
            float m1 = -1e30f, m2 = -1e30f;
            #pragma unroll
            for (int j = 0; j < 4; j++) {
                float v = sc[g*4 + j];
                if (v > m1) { m2 = m1; m1 = v; } else if (v > m2) m2 = v;
            }
            gs[g] = m1 + m2;
        }
        int g1 = 0;
        for (int g = 1; g < NG; g++) if (gs[g] > gs[g1]) g1 = g;
        int g2 = -1;
        for (int g = 0; g < NG; g++) {
            if (g == g1) continue;
            if (g2 < 0 || gs[g] > gs[g2]) g2 = g;
        }
        float msk[NE];
        #pragma unroll
        for (int i = 0; i < NE; i++) {
            int gi = i >> 2;
            msk[i] = (gi == g1 || gi == g2) ? sc[i] : 0.0f;
        }
        int idx[NK]; float tw[NK]; float sum = 0.f;
        #pragma unroll
        for (int k = 0; k < NK; k++) {
            int best = 0; float bv = -1e30f;
            for (int i = 0; i < NE; i++)
                if (msk[i] > bv) { bv = msk[i]; best = i; }
            msk[best] = -1e30f;
            idx[k] = best; tw[k] = scores[best]; sum += tw[k];
        }
        const float inv = RSCALE / (sum + 1e-20f);
        for (int k = 0; k < NK; k++) {
            g_texp[t*NK + k] = idx[k];
            g_twt[t*NK + k]  = tw[k] * inv;
            atomicAdd(&g_count[idx[k]], 1);
        }
    }
}

__global__ void prefix_kernel() {
    int o = 0;
    for (int e = 0; e < NE; e++) { g_off[e] = o; g_cur[e] = o; o += g_count[e]; }
    g_off[NE] = o;
}

__global__ void scatter_kernel() {
    int t = blockIdx.x*blockDim.x + threadIdx.x;
    if (t >= NT) return;
    for (int k = 0; k < NK; k++) {
        int e = g_texp[t*NK + k];
        int s = atomicAdd(&g_cur[e], 1);
        g_tok[s] = t;
        g_wslot[s] = g_twt[t*NK + k];
        g_slot[t*NK + k] = s;
    }
}

// ---------------- gate+up fused MMA (fp16, 2-product) ----------------
// CTA 128m x 64n per gemm. 8 warps: wr=wid>>1 (32m each), wc=wid&1 (32n each).
// smem per buffer (halves): A[128*SK] | Gh[64*SK] | Gls | Uh | Uls  = 384*SK
#define GU_BUFH (384*SK)
#define GU_SMEM (2*GU_BUFH*2 + 512)

__global__ __launch_bounds__(256, 2) void gateup_mma(
    const half* __restrict__ gwh, const half* __restrict__ gwls,
    const half* __restrict__ uwh, const half* __restrict__ uwls,
    half* __restrict__ hout, size_t estride, int outw, int routed)
{
    const int e = blockIdx.z;
    const int off = routed ? g_off[e] : 0;
    const int ne  = routed ? (g_off[e+1] - off) : NT;
    const int m0 = blockIdx.x * 128;
    if (m0 >= ne) return;
    const int n0 = blockIdx.y * 64;

    extern __shared__ half smem[];
    int* toks = (int*)(smem + 2*GU_BUFH);

    const int tid = threadIdx.x, wid = tid >> 5, lid = tid & 31;
    const int wr = wid >> 1, wc = wid & 1;
    if (tid < 128) {
        int m = m0 + tid;
        toks[tid] = (m < ne) ? (routed ? g_tok[off + m] : m) : -1;
    }
    __syncthreads();

    const half* gh = gwh + (size_t)e*estride;
    const half* gl = gwls + (size_t)e*estride;
    const half* uh = uwh + (size_t)e*estride;
    const half* ul = uwls + (size_t)e*estride;

    const int ar = tid >> 2, acc_ = tid & 3;        // A: row pair base, chunk
    const int bp = tid >> 6, brow = tid & 63;       // B: plane, row
    const half* bsrc = (bp == 0 ? gh : bp == 1 ? gl : bp == 2 ? uh : ul)
                       + (size_t)(n0 + brow)*NH;

    auto issue = [&](int c, int buf) {
        const int k0 = c * 32;
        half* bb = smem + buf*GU_BUFH;
        #pragma unroll
        for (int hh = 0; hh < 2; hh++) {
            int row = ar + hh*64;
            int tok = toks[row];
            int sz = (tok >= 0) ? 16 : 0;
            const half* src = g_xh + (size_t)(tok < 0 ? 0 : tok)*NH + k0 + acc_*8;
            cpa16(smem_u32(bb + row*SK + acc_*8), src, sz);
        }
        half* bdst = bb + (128 + bp*64 + brow)*SK;
        #pragma unroll
        for (int cc = 0; cc < 4; cc++)
            cpa16(smem_u32(bdst + cc*8), bsrc + k0 + cc*8, 16);
    };

    float accg[2][4][4] = {}, accu[2][4][4] = {};
    const int NC = NH/32;
    issue(0, 0); CP_COMMIT();
    for (int c = 0; c < NC; ++c) {
        const int buf = c & 1;
        if (c + 1 < NC) { issue(c+1, buf^1); CP_COMMIT(); CP_WAIT1(); }
        else CP_WAIT0();
        __syncthreads();
        const half* bb = smem + buf*GU_BUFH;
        const uint32_t aA = smem_u32(bb);
        const uint32_t aG = smem_u32(bb + 128*SK), aGl = smem_u32(bb + 192*SK);
        const uint32_t aU = smem_u32(bb + 256*SK), aUl = smem_u32(bb + 320*SK);
        #pragma unroll
        for (int ks = 0; ks < 32; ks += 16) {
            uint32_t ah[2][4], as[2][4];
            #pragma unroll
            for (int mi = 0; mi < 2; mi++) {
                uint32_t o = ((wr*32 + mi*16 + (lid & 15))*SK + ks + (lid >> 4)*8)*2;
                ldsm4(ah[mi][0], ah[mi][1], ah[mi][2], ah[mi][3], aA + o);
                #pragma unroll
                for (int j = 0; j < 4; j++) as[mi][j] = hscale(ah[mi][j]);
            }
            #pragma unroll
            for (int nip = 0; nip < 2; nip++) {
                uint32_t o = ((wc*32 + nip*16 + (lid & 7) + (lid >> 4)*8)*SK
                              + ks + ((lid >> 3) & 1)*8)*2;
                uint32_t bg[4], bgl[4], bu[4], bul[4];
                ldsm4(bg[0], bg[1], bg[2], bg[3], aG + o);
                ldsm4(bgl[0], bgl[1], bgl[2], bgl[3], aGl + o);
                ldsm4(bu[0], bu[1], bu[2], bu[3], aU + o);
                ldsm4(bul[0], bul[1], bul[2], bul[3], aUl + o);
                #pragma unroll
                for (int q = 0; q < 2; q++) {
                    const int ni = nip*2 + q;
                    #pragma unroll
                    for (int mi = 0; mi < 2; mi++) {
                        mma16816(accg[mi][ni], ah[mi], bg + q*2);
                        mma16816(accg[mi][ni], as[mi], bgl + q*2);
                        mma16816(accu[mi][ni], ah[mi], bu + q*2);
                        mma16816(accu[mi][ni], as[mi], bul + q*2);
                    }
                }
            }
        }
        __syncthreads();
    }
    // epilogue: h = silu(g)*u -> fp16
    #pragma unroll
    for (int mi = 0; mi < 2; mi++) {
        int r0 = wr*32 + mi*16 + (lid >> 2);
        #pragma unroll
        for (int half_ = 0; half_ < 2; half_++) {
            int m = m0 + r0 + half_*8;
            if (m >= ne) continue;
            size_t orow = (size_t)(off + m) * outw;
            #pragma unroll
            for (int ni = 0; ni < 4; ni++) {
                float g0 = accg[mi][ni][half_*2+0], g1 = accg[mi][ni][half_*2+1];
                float u0 = accu[mi][ni][half_*2+0], u1 = accu[mi][ni][half_*2+1];
                float h0 = g0 / (1.f + expf(-g0)) * u0;
                float h1 = g1 / (1.f + expf(-g1)) * u1;
                int nc = n0 + wc*32 + ni*8 + (lid & 3)*2;
                *(__half2*)(hout + orow + nc) = __half2(__float2half(h0), __float2half(h1));
            }
        }
    }
}

// ---------------- down projection MMA (fp16, 2-product) ----------------
// CTA 128m x 128n. 8 warps: wr=wid>>2 (64m), wc=wid&3 (32n).
// smem per buffer (halves): A[128*SK] | Bh[128*SK] | Bls[128*SK] = 384*SK
#define DN_BUFH (384*SK)
#define DN_SMEM (2*DN_BUFH*2)

__global__ __launch_bounds__(256, 2) void down_mma(
    const half* __restrict__ asrc,
    const half* __restrict__ dwh, const half* __restrict__ dwls,
    float* __restrict__ dst, int Kd, size_t estride, int routed)
{
    const int e = blockIdx.z;
    const int off = routed ? g_off[e] : 0;
    const int ne  = routed ? (g_off[e+1] - off) : NT;
    const int m0 = blockIdx.x * 128;
    if (m0 >= ne) return;
    const int n0 = blockIdx.y * 128;

    extern __shared__ half smem[];
    const int tid = threadIdx.x, wid = tid >> 5, lid = tid & 31;
    const int wr = wid >> 2, wc = wid & 3;

    const half* bh = dwh + (size_t)e*estride;
    const half* bl = dwls + (size_t)e*estride;

    const int ar = tid >> 2, acc_ = tid & 3;
    const int bp = tid >> 7, brow = tid & 127;   // 2 planes, 128 threads each
    const half* bsrc = (bp == 0 ? bh : bl) + (size_t)(n0 + brow)*Kd;

    auto issue = [&](int c, int buf) {
        const int k0 = c * 32;
        half* bb = smem + buf*DN_BUFH;
        #pragma unroll
        for (int hh = 0; hh < 2; hh++) {
            int row = ar + hh*64;
            int m = m0 + row;
            int sz = (m < ne) ? 16 : 0;
            const half* src = asrc + (size_t)(off + (m < ne ? m : 0))*Kd + k0 + acc_*8;
            cpa16(smem_u32(bb + row*SK + acc_*8), src, sz);
        }
        half* bdst = bb + (128 + bp*128 + brow)*SK;
        #pragma unroll
        for (int cc = 0; cc < 2; cc++)
            cpa16(smem_u32(bdst + cc*8 + (tid & 0 ? 0 : 0)), bsrc + k0 + cc*8, 16);
        // remaining two chunks
        #pragma unroll
        for (int cc = 2; cc < 4; cc++)
            cpa16(smem_u32(bdst + cc*8), bsrc + k0 + cc*8, 16);
    };

    float acc[4][4][4] = {};
    const int NC = Kd/32;
    issue(0, 0); CP_COMMIT();
    for (int c = 0; c < NC; ++c) {
        const int buf = c & 1;
        if (c + 1 < NC) { issue(c+1, buf^1); CP_COMMIT(); CP_WAIT1(); }
        else CP_WAIT0();
        __syncthreads();
        const half* bb = smem + buf*DN_BUFH;
        const uint32_t aA = smem_u32(bb);
        const uint32_t aB = smem_u32(bb + 128*SK), aBl = smem_u32(bb + 256*SK);
        #pragma unroll
        for (int ks = 0; ks < 32; ks += 16) {
            uint32_t ah[4][4];
            #pragma unroll
            for (int mi = 0; mi < 4; mi++) {
                uint32_t o = ((wr*64 + mi*16 + (lid & 15))*SK + ks + (lid >> 4)*8)*2;
                ldsm4(ah[mi][0], ah[mi][1], ah[mi][2], ah[mi][3], aA + o);
            }
            #pragma unroll
            for (int nip = 0; nip < 2; nip++) {
                uint32_t o = ((wc*32 + nip*16 + (lid & 7) + (lid >> 4)*8)*SK
                              + ks + ((lid >> 3) & 1)*8)*2;
                uint32_t bbh[4], bbl[4];
                ldsm4(bbh[0], bbh[1], bbh[2], bbh[3], aB + o);
                ldsm4(bbl[0], bbl[1], bbl[2], bbl[3], aBl + o);
                #pragma unroll
                for (int mi = 0; mi < 4; mi++) {
                    uint32_t as[4];
                    #pragma unroll
                    for (int j = 0; j < 4; j++) as[j] = hscale(ah[mi][j]);
                    #pragma unroll
                    for (int q = 0; q < 2; q++) {
                        const int ni = nip*2 + q;
                        mma16816(acc[mi][ni], ah[mi], bbh + q*2);
                        mma16816(acc[mi][ni], as,     bbl + q*2);
                    }
                }
            }
        }
        __syncthreads();
    }
    // epilogue
    #pragma unroll
    for (int mi = 0; mi < 4; mi++) {
        int r0 = wr*64 + mi*16 + (lid >> 2);
        #pragma unroll
        for (int half_ = 0; half_ < 2; half_++) {
            int m = m0 + r0 + half_*8;
            if (m >= ne) continue;
            float w = routed ? g_wslot[off + m] : 1.f;
            size_t orow = (size_t)(off + m) * NH;
            #pragma unroll
            for (int ni = 0; ni < 4; ni++) {
                int nc = n0 + wc*32 + ni*8 + (lid & 3)*2;
                float2 o;
                o.x = acc[mi][ni][half_*2+0] * w;
                o.y = acc[mi][ni][half_*2+1] * w;
                *(float2*)(dst + orow + nc) = o;
            }
        }
    }
}

// out[t] += sum_k y[slot[t,k]]
__global__ void combine_kernel(float* __restrict__ out) {
    const int t = blockIdx.x;
    const int c = threadIdx.x;
    const int s0 = g_slot[t*4+0], s1 = g_slot[t*4+1],
              s2 = g_slot[t*4+2], s3 = g_slot[t*4+3];
    const float4* y4 = (const float4*)g_y;
    float4* o4 = (float4*)out;
    float4 o = o4[(size_t)t*256 + c];
    float4 a = y4[(size_t)s0*256 + c];
    float4 b = y4[(size_t)s1*256 + c];
    float4 cc = y4[(size_t)s2*256 + c];
    float4 d = y4[(size_t)s3*256 + c];
    o.x += a.x + b.x + cc.x + d.x;
    o.y += a.y + b.y + cc.y + d.y;
    o.z += a.z + b.z + cc.z + d.z;
    o.w += a.w + b.w + cc.w + d.w;
    o4[(size_t)t*256 + c] = o;
}

extern "C" void kernel_launch(void* const* d_in, const int* in_sizes, int n_in,
                              void* d_out, int out_size) {
    const float* x   = (const float*)d_in[0];
    const float* wr  = (const float*)d_in[1];
    const float* eb  = (const float*)d_in[2];
    const float* gw  = (const float*)d_in[3];
    const float* uw  = (const float*)d_in[4];
    const float* dw  = (const float*)d_in[5];
    const float* sgw = (const float*)d_in[6];
    const float* suw = (const float*)d_in[7];
    const float* sdw = (const float*)d_in[8];
    float* out = (float*)d_out;
    (void)in_sizes; (void)n_in; (void)out_size;

    static bool attr_set = false;
    cudaFuncSetAttribute(gateup_mma, cudaFuncAttributeMaxDynamicSharedMemorySize, GU_SMEM);
    cudaFuncSetAttribute(down_mma,  cudaFuncAttributeMaxDynamicSharedMemorySize, DN_SMEM);
    (void)attr_set;

    half *xh, *hh, *shh, *gwh, *gwls, *uwh, *uwls, *dwh, *dwls;
    half *sgwh, *sgwls, *suwh, *suwls, *sdwh, *sdwls;
    cudaGetSymbolAddress((void**)&xh,  g_xh);
    cudaGetSymbolAddress((void**)&hh,  g_hh);
    cudaGetSymbolAddress((void**)&shh, g_shh);
    cudaGetSymbolAddress((void**)&gwh, g_gwh);  cudaGetSymbolAddress((void**)&gwls, g_gwls);
    cudaGetSymbolAddress((void**)&uwh, g_uwh);  cudaGetSymbolAddress((void**)&uwls, g_uwls);
    cudaGetSymbolAddress((void**)&dwh, g_dwh);  cudaGetSymbolAddress((void**)&dwls, g_dwls);
    cudaGetSymbolAddress((void**)&sgwh, g_sgwh); cudaGetSymbolAddress((void**)&sgwls, g_sgwls);
    cudaGetSymbolAddress((void**)&suwh, g_suwh); cudaGetSymbolAddress((void**)&suwls, g_suwls);
    cudaGetSymbolAddress((void**)&sdwh, g_sdwh); cudaGetSymbolAddress((void**)&sdwls, g_sdwls);
    float* yb;
    cudaGetSymbolAddress((void**)&yb, g_y);

    // conversions
    const int NW = NE*NI*NH;            // 8.4M
    const int NS = NISH*NH;             // 1M
    conv_pair_kernel<<<NW/1024, 256>>>(gw,  gwh,  gwls,  NW);
    conv_pair_kernel<<<NW/1024, 256>>>(uw,  uwh,  uwls,  NW);
    conv_pair_kernel<<<NW/1024, 256>>>(dw,  dwh,  dwls,  NW);
    conv_pair_kernel<<<NS/1024, 256>>>(sgw, sgwh, sgwls, NS);
    conv_pair_kernel<<<NS/1024, 256>>>(suw, suwh, suwls, NS);
    conv_pair_kernel<<<NS/1024, 256>>>(sdw, sdwh, sdwls, NS);
    conv_hi_kernel<<<(NT*NH)/1024, 256>>>(x, xh, NT*NH);

    zero_kernel<<<1, 32>>>();
    router_kernel<<<NT, 128>>>(x, wr, eb);
    prefix_kernel<<<1, 1>>>();
    scatter_kernel<<<8, 256>>>();

    // routed gate+up: N = 512, K = 1024
    gateup_mma<<<dim3(64, NI/64, NE), 256, GU_SMEM>>>(
        gwh, gwls, uwh, uwls, hh, (size_t)NI*NH, NI, 1);
    // shared gate+up: N = 1024, K = 1024
    gateup_mma<<<dim3(NT/128, NISH/64, 1), 256, GU_SMEM>>>(
        sgwh, sgwls, suwh, suwls, shh, 0, NISH, 0);
    // routed down: K = 512, N = 1024
    down_mma<<<dim3(64, NH/128, NE), 256, DN_SMEM>>>(
        hh, dwh, dwls, yb, NI, (size_t)NH*NI, 1);
    // shared down: K = 1024, N = 1024 (writes out)
    down_mma<<<dim3(NT/128, NH/128, 1), 256, DN_SMEM>>>(
        shh, sdwh, sdwls, out, NISH, 0, 0);

    combine_kernel<<<NT, 256>>>(out);
}